// round 17
// baseline (speedup 1.0000x reference)
#include <cuda_runtime.h>
#include <cuda_fp16.h>
#include <stdint.h>

#define NB_COUNT 32
#define DIM 128            // floats per row
#define NUM_IDS 100000     // problem constant (table rows)

// fp16 shadow table: 100000 x 128 halves = 25.6 MB device scratch
// (L2-resident). One warp gathers a full 256B row with a single LDG.64.
__device__ __align__(16) __half g_emb_h[(size_t)NUM_IDS * DIM];

// Conversion pass: each thread converts 8 floats -> 8 halves,
// 2x LDG.128 (streaming) + 1x STG.128. Bandwidth-bound (~9.6us for 77MB).
__global__ __launch_bounds__(256) void convert_kernel(
    const float4* __restrict__ emb, int n8)   // n8 = NUM_IDS*DIM/8
{
    const int i = blockIdx.x * blockDim.x + threadIdx.x;
    if (i >= n8) return;
    const float4 v0 = __ldcs(&emb[2 * i]);
    const float4 v1 = __ldcs(&emb[2 * i + 1]);
    const __half2 h0 = __floats2half2_rn(v0.x, v0.y);
    const __half2 h1 = __floats2half2_rn(v0.z, v0.w);
    const __half2 h2 = __floats2half2_rn(v1.x, v1.y);
    const __half2 h3 = __floats2half2_rn(v1.z, v1.w);
    uint4 packed;
    packed.x = *(const unsigned*)&h0;
    packed.y = *(const unsigned*)&h1;
    packed.z = *(const unsigned*)&h2;
    packed.w = *(const unsigned*)&h3;
    ((uint4*)g_emb_h)[i] = packed;   // 16B coalesced store
}

// One warp per node; one LDG.64 per neighbor row; 4-deep fp16 tree.
// fma-pipe work per 4 rows: 6 HADD2 + 2 cvt-pairs + 2 FADD-pairs = 10
// warp-instr (vs 20 for pairwise), pushing the fma pipe (~20%) well under
// the L1tex wavefront floor (10.8K rows/SM x 3.07 cyc ~ 22us).
// Precision: two fp16 rounding levels on O(1) operands -> ~5e-4 rel,
// under the 1e-3 tolerance (measured 3.06e-4 at one level).
__global__ __launch_bounds__(256, 8) void sum_agg_kernel(
    const int* __restrict__ neighs,
    float4* __restrict__ out,         // [node_count][32] float4
    int node_count)
{
    const int warp = (blockIdx.x * blockDim.x + threadIdx.x) >> 5;
    const int lane = threadIdx.x & 31;
    if (warp >= node_count) return;

    // Coalesced index load: lane l gets neighbor l of this node.
    const int my_idx = neighs[(size_t)warp * NB_COUNT + lane];

    float a0 = 0.f, a1 = 0.f, a2 = 0.f, a3 = 0.f;

    const uint2* table = (const uint2*)g_emb_h;   // 32 uint2 per row

    #pragma unroll
    for (int j = 0; j < NB_COUNT; j += 4) {
        const int r0 = __shfl_sync(0xffffffffu, my_idx, j);
        const int r1 = __shfl_sync(0xffffffffu, my_idx, j + 1);
        const int r2 = __shfl_sync(0xffffffffu, my_idx, j + 2);
        const int r3 = __shfl_sync(0xffffffffu, my_idx, j + 3);
        const uint2 ra = __ldg(table + (size_t)r0 * 32 + lane);  // LDG.64
        const uint2 rb = __ldg(table + (size_t)r1 * 32 + lane);
        const uint2 rc = __ldg(table + (size_t)r2 * 32 + lane);
        const uint2 rd = __ldg(table + (size_t)r3 * 32 + lane);
        // fp16 tree: (a+b) + (c+d), then one f32 accumulate per group of 4.
        const __half2 sab0 = __hadd2(*(const __half2*)&ra.x, *(const __half2*)&rb.x);
        const __half2 sab1 = __hadd2(*(const __half2*)&ra.y, *(const __half2*)&rb.y);
        const __half2 scd0 = __hadd2(*(const __half2*)&rc.x, *(const __half2*)&rd.x);
        const __half2 scd1 = __hadd2(*(const __half2*)&rc.y, *(const __half2*)&rd.y);
        const __half2 s0 = __hadd2(sab0, scd0);
        const __half2 s1 = __hadd2(sab1, scd1);
        const float2 f0 = __half22float2(s0);
        const float2 f1 = __half22float2(s1);
        a0 += f0.x; a1 += f0.y; a2 += f1.x; a3 += f1.y;
    }

    // Streaming store: written once, must not evict the fp16 shadow from L2.
    __stcs(&out[(size_t)warp * 32 + lane], make_float4(a0, a1, a2, a3));
}

extern "C" void kernel_launch(void* const* d_in, const int* in_sizes, int n_in,
                              void* d_out, int out_size)
{
    // metadata order: neighs (int32), node_count (int scalar), emb_table (f32)
    const int* neighs = (const int*)d_in[0];
    const float4* emb = (const float4*)d_in[2];
    float4* out = (float4*)d_out;

    const int node_count = out_size / DIM;     // out is [node_count, 128] f32
    const int n8 = in_sizes[2] / 8;            // 8 floats per convert thread

    // Pass 1: build fp16 shadow table (wide, streaming).
    convert_kernel<<<(n8 + 255) / 256, 256>>>(emb, n8);

    // Pass 2: gather-sum from the fp16 table.
    const int threads = 256;                    // 8 warps = 8 nodes per block
    const int blocks = (node_count * 32 + threads - 1) / threads;
    sum_agg_kernel<<<blocks, threads>>>(neighs, out, node_count);
}